// round 12
// baseline (speedup 1.0000x reference)
#include <cuda_runtime.h>
#include <cuda_fp16.h>
#include <cuda_bf16.h>
#include <cstdint>

// ---------------- problem constants ----------------
#define BB 8
#define TT 1024
#define DD 1024
#define FF 4096
#define MM (BB * TT)          // 8192 rows
#define EPS_LN 1e-3f

// ---------------- PTX helpers ----------------
__device__ __forceinline__ uint32_t smem_u32(const void* p) {
    uint32_t a;
    asm("{ .reg .u64 t; cvta.to.shared.u64 t, %1; cvt.u32.u64 %0, t; }"
        : "=r"(a) : "l"(p));
    return a;
}

__device__ __forceinline__ void cpa16(uint32_t dst, const void* src) {
    asm volatile("cp.async.cg.shared.global [%0], [%1], 16;"
                 :: "r"(dst), "l"(src) : "memory");
}
#define CP_COMMIT() asm volatile("cp.async.commit_group;" ::: "memory")
#define CP_WAIT(n)  asm volatile("cp.async.wait_group %0;" :: "n"(n) : "memory")

__device__ __forceinline__ void ldsm4(uint32_t* r, uint32_t a) {
    asm volatile("ldmatrix.sync.aligned.m8n8.x4.shared.b16 {%0,%1,%2,%3}, [%4];"
                 : "=r"(r[0]), "=r"(r[1]), "=r"(r[2]), "=r"(r[3]) : "r"(a));
}

__device__ __forceinline__ void mma_fp16(float* c, const uint32_t* a, const uint32_t* b) {
    asm volatile(
        "mma.sync.aligned.m16n8k16.row.col.f32.f16.f16.f32 "
        "{%0,%1,%2,%3}, {%4,%5,%6,%7}, {%8,%9}, {%0,%1,%2,%3};"
        : "+f"(c[0]), "+f"(c[1]), "+f"(c[2]), "+f"(c[3])
        : "r"(a[0]), "r"(a[1]), "r"(a[2]), "r"(a[3]), "r"(b[0]), "r"(b[1]));
}

// ---------------- scratch (static device globals) ----------------
__device__ float g_xn [(size_t)MM * DD];
__device__ float g_kb [(size_t)MM * DD];
__device__ float g_vb [(size_t)MM * DD];
__device__ float g_rb [(size_t)MM * DD];
__device__ float g_wkv[(size_t)MM * DD];
__device__ float g_x1 [(size_t)MM * DD];
__device__ float g_xn2[(size_t)MM * DD];
__device__ float g_rc [(size_t)MM * DD];
// fp16 activations
__device__ __half g_ak[(size_t)MM * DD];
__device__ __half g_av[(size_t)MM * DD];
__device__ __half g_ar[(size_t)MM * DD];
__device__ __half g_kc[(size_t)MM * FF];
// fp16 transposed weights [N, K]
__device__ __half g_wk[(size_t)DD * DD];
__device__ __half g_wv[(size_t)DD * DD];
__device__ __half g_wr[(size_t)DD * DD];
__device__ __half g_wo[(size_t)DD * DD];
__device__ __half g_cr[(size_t)DD * DD];
__device__ __half g_ck[(size_t)FF * DD];   // Ck^T
__device__ __half g_cv[(size_t)DD * FF];   // Cv^T

// ---------------- LayerNorm ----------------
__global__ __launch_bounds__(256)
void ln_kernel(const float* __restrict__ x, const float* __restrict__ gamma,
               const float* __restrict__ beta, float* __restrict__ y,
               float* __restrict__ last_out) {
    __shared__ float red0[8], red1[8];
    int row = blockIdx.x;
    const float* xr = x + (size_t)row * DD;
    float s = 0.f, s2 = 0.f;
    #pragma unroll
    for (int i = threadIdx.x; i < DD; i += 256) {
        float v = xr[i];
        s += v; s2 += v * v;
    }
    #pragma unroll
    for (int o = 16; o; o >>= 1) {
        s  += __shfl_down_sync(0xffffffffu, s,  o);
        s2 += __shfl_down_sync(0xffffffffu, s2, o);
    }
    int lane = threadIdx.x & 31, wid = threadIdx.x >> 5;
    if (lane == 0) { red0[wid] = s; red1[wid] = s2; }
    __syncthreads();
    s = 0.f; s2 = 0.f;
    #pragma unroll
    for (int i = 0; i < 8; i++) { s += red0[i]; s2 += red1[i]; }
    const float invD = 1.0f / DD;
    float mu  = s * invD;
    float var = s2 * invD - mu * mu;
    float inv = rsqrtf(var + EPS_LN);
    float* yr = y + (size_t)row * DD;
    bool is_last = ((row & (TT - 1)) == (TT - 1));
    float* lr = last_out + (size_t)(row >> 10) * DD;
    #pragma unroll
    for (int i = threadIdx.x; i < DD; i += 256) {
        float v = (xr[i] - mu) * inv * gamma[i] + beta[i];
        yr[i] = v;
        if (is_last) lr[i] = v;
    }
}

// ---------------- token-shift mix -> fp16 ----------------
__global__ __launch_bounds__(256)
void mix_h(const float* __restrict__ xn, const float* __restrict__ init,
           const float* __restrict__ mk, const float* __restrict__ mv,
           const float* __restrict__ mr,
           __half* __restrict__ ok, __half* __restrict__ ov,
           __half* __restrict__ orr) {
    size_t idx = (size_t)blockIdx.x * 256 + threadIdx.x;
    int d = (int)(idx & (DD - 1));
    size_t row = idx >> 10;
    int t = (int)(row & (TT - 1));
    int b = (int)(row >> 10);
    float cur  = xn[idx];
    float prev = t ? xn[idx - DD] : init[(size_t)b * DD + d];
    float m;
    m = mk[d]; ok[idx]  = __float2half(m * cur + (1.f - m) * prev);
    if (ov) { m = mv[d]; ov[idx] = __float2half(m * cur + (1.f - m) * prev); }
    m = mr[d]; orr[idx] = __float2half(m * cur + (1.f - m) * prev);
}

// ---------------- r * wkv -> fp16 ----------------
__global__ __launch_bounds__(256)
void mul_h(const float* __restrict__ a, const float* __restrict__ b,
           __half* __restrict__ o) {
    size_t idx = (size_t)blockIdx.x * 256 + threadIdx.x;
    o[idx] = __float2half(a[idx] * b[idx]);
}

// ---------------- weight convert + transpose: W[K,N] fp32 -> WT [N,K] fp16 ----------------
__global__ __launch_bounds__(256)
void wconv_t(const float* __restrict__ W, __half* __restrict__ o,
             int Kdim, int Ndim) {
    __shared__ float t[32][33];
    int n0 = blockIdx.x * 32, k0 = blockIdx.y * 32;
    int tx = threadIdx.x, ty = threadIdx.y;
    #pragma unroll
    for (int i = ty; i < 32; i += 8)
        t[i][tx] = W[(size_t)(k0 + i) * Ndim + n0 + tx];
    __syncthreads();
    #pragma unroll
    for (int i = ty; i < 32; i += 8)
        o[(size_t)(n0 + i) * Kdim + k0 + tx] = __float2half(t[tx][i]);
}

// ---------------- WKV scan ----------------
__global__ __launch_bounds__(64)
void wkv_scan(const float* __restrict__ kbuf, const float* __restrict__ vbuf,
              const float* __restrict__ a0, const float* __restrict__ b0,
              const float* __restrict__ p0,
              const float* __restrict__ decay, const float* __restrict__ first,
              float* __restrict__ wkvbuf,
              float* __restrict__ aa_out, float* __restrict__ bb_out,
              float* __restrict__ pp_out) {
    int idx = blockIdx.x * 64 + threadIdx.x;   // 0 .. B*D-1
    int d = idx & (DD - 1);
    int b = idx >> 10;
    float w = -__expf(decay[d]);
    float u = first[d];
    float aa = a0[idx], bb = b0[idx], pp = p0[idx];
    const float* kp = kbuf + (size_t)b * TT * DD + d;
    const float* vp = vbuf + (size_t)b * TT * DD + d;
    float* op = wkvbuf + (size_t)b * TT * DD + d;
    #pragma unroll 4
    for (int t = 0; t < TT; t++) {
        float kt = kp[(size_t)t * DD];
        float vt = vp[(size_t)t * DD];
        float ww = u + kt;
        float p  = fmaxf(pp, ww);
        float e1 = __expf(pp - p);
        float e2 = __expf(ww - p);
        op[(size_t)t * DD] = (e1 * aa + e2 * vt) / (e1 * bb + e2);
        float ww2 = pp + w;
        float p2  = fmaxf(ww2, kt);
        float e1b = __expf(ww2 - p2);
        float e2b = __expf(kt - p2);
        aa = e1b * aa + e2b * vt;
        bb = e1b * bb + e2b;
        pp = p2;
    }
    aa_out[idx] = aa; bb_out[idx] = bb; pp_out[idx] = pp;
}

// ---------------- fp16 mma.sync GEMM (multi-problem via grid.z) ----------------
// CTA tile 256x128, BK=32, 512 threads / 16 warps (warp tile 64x32), 5-stage cp.async.
#define ROWP 80                         // smem row pitch bytes (32 fp16 + 8 pad)
#define OFF_B 20480                     // A = 256*80
#define STAGEB 30720                    // A + B
#define NSTAGE 5
#define GEMM_SMEM (NSTAGE * STAGEB)     // 153600

struct GemmArgs {
    const __half* A;      // [M, K]
    const __half* W;      // [N, K]
    int Kn, Nn;
    float* Cf;            // fp32 out (or null)
    __half* Ch;           // fp16 out (or null)
    int act;              // 0 none, 1 sigmoid, 2 relu^2
    const float* mulp;
    const float* addp;
    int nx;               // active blockIdx.x count
};

__device__ __forceinline__ void epi_pair(float v0, float v1, size_t base,
                                         int act,
                                         const float* __restrict__ mulp,
                                         const float* __restrict__ addp,
                                         float* __restrict__ Cf,
                                         __half* __restrict__ Ch) {
    if (act == 1) {
        v0 = 1.f / (1.f + __expf(-v0));
        v1 = 1.f / (1.f + __expf(-v1));
    } else if (act == 2) {
        v0 = fmaxf(v0, 0.f); v0 *= v0;
        v1 = fmaxf(v1, 0.f); v1 *= v1;
    }
    if (mulp) { float2 m = *(const float2*)(mulp + base); v0 *= m.x; v1 *= m.y; }
    if (addp) { float2 a = *(const float2*)(addp + base); v0 += a.x; v1 += a.y; }
    if (Cf) { float2 o; o.x = v0; o.y = v1; *(float2*)(Cf + base) = o; }
    if (Ch) {
        __half2 h = __floats2half2_rn(v0, v1);
        *(__half2*)(Ch + base) = h;
    }
}

__global__ __launch_bounds__(512, 1)
void mma_gemm(GemmArgs ga0, GemmArgs ga1, GemmArgs ga2) {
    const GemmArgs g = (blockIdx.z == 0) ? ga0 : (blockIdx.z == 1) ? ga1 : ga2;
    if ((int)blockIdx.x >= g.nx) return;

    extern __shared__ char sm[];
    const uint32_t sbase = smem_u32(sm);
    const int tid = threadIdx.x;
    const int lane = tid & 31, wid = tid >> 5;
    const int m0 = blockIdx.y * 256, n0 = blockIdx.x * 128;
    const int Kn = g.Kn, Nn = g.Nn;
    const int KT = Kn >> 5;
    const int wm = (wid >> 2) * 64;   // warp m offset (0..192)
    const int wn = (wid & 3) * 32;    // warp n offset (0..96)
    const __half* __restrict__ A  = g.A;
    const __half* __restrict__ Bw = g.W;

    float acc[4][4][4];
    #pragma unroll
    for (int t = 0; t < 4; t++)
        #pragma unroll
        for (int j = 0; j < 4; j++)
            #pragma unroll
            for (int q = 0; q < 4; q++) acc[t][j][q] = 0.f;

    auto issue = [&](int kt) {
        const int slot = kt % NSTAGE;
        const uint32_t st = sbase + slot * STAGEB;
        const size_t k0 = (size_t)kt << 5;
        #pragma unroll
        for (int h = 0; h < 2; h++) {
            int idx = tid + h * 512;
            int row = idx >> 2, ch = idx & 3;
            cpa16(st + (uint32_t)row * ROWP + ch * 16,
                  A + (size_t)(m0 + row) * Kn + k0 + ch * 8);
        }
        {
            int row = tid >> 2, ch = tid & 3;
            cpa16(st + OFF_B + (uint32_t)row * ROWP + ch * 16,
                  Bw + (size_t)(n0 + row) * Kn + k0 + ch * 8);
        }
        CP_COMMIT();
    };

    issue(0);
    issue(1);
    issue(2);
    issue(3);

    for (int kt = 0; kt < KT; kt++) {
        CP_WAIT(3);
        __syncthreads();
        const uint32_t st = sbase + (kt % NSTAGE) * STAGEB;

        // ---- load ALL fragments for both k-slices up front ----
        uint32_t ah[2][4][4], bh[2][4][2];
        #pragma unroll
        for (int ks = 0; ks < 2; ks++) {
            const int k0 = ks * 16;
            #pragma unroll
            for (int t = 0; t < 4; t++) {
                uint32_t ad = st + (uint32_t)(wm + t * 16 + (lane & 15)) * ROWP
                            + (k0 + (lane >> 4) * 8) * 2;
                ldsm4(ah[ks][t], ad);
            }
            {
                int gq = lane >> 3, r = lane & 7;
                int n = wn + (gq >> 1) * 8 + r;
                int k = k0 + (gq & 1) * 8;
                uint32_t bd = st + OFF_B + (uint32_t)n * ROWP + k * 2;
                ldsm4(&bh[ks][0][0], bd);
                ldsm4(&bh[ks][2][0], bd + 16 * ROWP);
            }
        }

        // ---- overlap next-stage loads with the MMA block ----
        if (kt + 4 < KT) issue(kt + 4);

        #pragma unroll
        for (int ks = 0; ks < 2; ks++)
            #pragma unroll
            for (int t = 0; t < 4; t++)
                #pragma unroll
                for (int j = 0; j < 4; j++)
                    mma_fp16(acc[t][j], ah[ks][t], bh[ks][j]);
    }
    CP_WAIT(0);

    // ---- epilogue ----
    #pragma unroll
    for (int t = 0; t < 4; t++) {
        int row = m0 + wm + t * 16 + (lane >> 2);
        #pragma unroll
        for (int j = 0; j < 4; j++) {
            int col = n0 + wn + j * 8 + ((lane & 3) << 1);
            size_t b0 = (size_t)row * Nn + col;
            size_t b1 = (size_t)(row + 8) * Nn + col;
            epi_pair(acc[t][j][0], acc[t][j][1], b0, g.act, g.mulp, g.addp, g.Cf, g.Ch);
            epi_pair(acc[t][j][2], acc[t][j][3], b1, g.act, g.mulp, g.addp, g.Cf, g.Ch);
        }
    }
}

// ---------------- host driver ----------------
extern "C" void kernel_launch(void* const* d_in, const int* in_sizes, int n_in,
                              void* d_out, int out_size) {
    const float* x        = (const float*)d_in[0];
    const float* att_x    = (const float*)d_in[1];
    const float* att_a    = (const float*)d_in[2];
    const float* att_b    = (const float*)d_in[3];
    const float* att_p    = (const float*)d_in[4];
    const float* ffn_x    = (const float*)d_in[5];
    const float* ln1_g    = (const float*)d_in[6];
    const float* ln1_b    = (const float*)d_in[7];
    const float* ln2_g    = (const float*)d_in[8];
    const float* ln2_b    = (const float*)d_in[9];
    const float* tm_mix_k = (const float*)d_in[10];
    const float* tm_mix_v = (const float*)d_in[11];
    const float* tm_mix_r = (const float*)d_in[12];
    const float* tm_decay = (const float*)d_in[13];
    const float* tm_first = (const float*)d_in[14];
    const float* Wk       = (const float*)d_in[15];
    const float* Wv       = (const float*)d_in[16];
    const float* Wr       = (const float*)d_in[17];
    const float* Wo       = (const float*)d_in[18];
    const float* cm_mix_k = (const float*)d_in[19];
    const float* cm_mix_r = (const float*)d_in[20];
    const float* Ck       = (const float*)d_in[21];
    const float* Cr       = (const float*)d_in[22];
    const float* Cv       = (const float*)d_in[23];

    float* out      = (float*)d_out;
    float* xn_last  = out + (size_t)MM * DD;
    float* aa_out   = xn_last  + (size_t)BB * DD;
    float* bb_out   = aa_out   + (size_t)BB * DD;
    float* pp_out   = bb_out   + (size_t)BB * DD;
    float* xn2_last = pp_out   + (size_t)BB * DD;

    float *xn, *kb, *vb, *rb, *wkv, *x1, *xn2, *rc;
    __half *ak, *av, *ar, *kc;
    __half *wk, *wv, *wr, *wo, *cr, *ck, *cv;
    cudaGetSymbolAddress((void**)&xn,  g_xn);
    cudaGetSymbolAddress((void**)&kb,  g_kb);
    cudaGetSymbolAddress((void**)&vb,  g_vb);
    cudaGetSymbolAddress((void**)&rb,  g_rb);
    cudaGetSymbolAddress((void**)&wkv, g_wkv);
    cudaGetSymbolAddress((void**)&x1,  g_x1);
    cudaGetSymbolAddress((void**)&xn2, g_xn2);
    cudaGetSymbolAddress((void**)&rc,  g_rc);
    cudaGetSymbolAddress((void**)&ak,  g_ak);
    cudaGetSymbolAddress((void**)&av,  g_av);
    cudaGetSymbolAddress((void**)&ar,  g_ar);
    cudaGetSymbolAddress((void**)&kc,  g_kc);
    cudaGetSymbolAddress((void**)&wk,  g_wk);
    cudaGetSymbolAddress((void**)&wv,  g_wv);
    cudaGetSymbolAddress((void**)&wr,  g_wr);
    cudaGetSymbolAddress((void**)&wo,  g_wo);
    cudaGetSymbolAddress((void**)&cr,  g_cr);
    cudaGetSymbolAddress((void**)&ck,  g_ck);
    cudaGetSymbolAddress((void**)&cv,  g_cv);

    cudaFuncSetAttribute(mma_gemm, cudaFuncAttributeMaxDynamicSharedMemorySize, GEMM_SMEM);

    const int ELT_BLOCKS = (int)(((size_t)MM * DD) / 256);  // 32768
    dim3 wt_thr(32, 8);

    auto mk = [](const __half* A, const __half* W, int Kn, int Nn,
                 float* Cf, __half* Ch, int act,
                 const float* mulp, const float* addp, int nx) {
        GemmArgs g;
        g.A = A; g.W = W; g.Kn = Kn; g.Nn = Nn;
        g.Cf = Cf; g.Ch = Ch; g.act = act;
        g.mulp = mulp; g.addp = addp; g.nx = nx;
        return g;
    };

    // ---- time mixing ----
    wconv_t<<<dim3(DD/32, DD/32), wt_thr>>>(Wk, wk, DD, DD);                  // 0
    wconv_t<<<dim3(DD/32, DD/32), wt_thr>>>(Wv, wv, DD, DD);                  // 1
    wconv_t<<<dim3(DD/32, DD/32), wt_thr>>>(Wr, wr, DD, DD);                  // 2
    ln_kernel<<<MM, 256>>>(x, ln1_g, ln1_b, xn, xn_last);                     // 3
    mix_h<<<ELT_BLOCKS, 256>>>(xn, att_x, tm_mix_k, tm_mix_v, tm_mix_r,
                               ak, av, ar);                                   // 4

    GemmArgs gk = mk(ak, wk, DD, DD, kb, nullptr, 0, nullptr, nullptr, 8);
    GemmArgs gv = mk(av, wv, DD, DD, vb, nullptr, 0, nullptr, nullptr, 8);
    GemmArgs gr = mk(ar, wr, DD, DD, rb, nullptr, 1, nullptr, nullptr, 8);
    mma_gemm<<<dim3(8, 32, 3), 512, GEMM_SMEM>>>(gk, gv, gr);                 // 5 <- profiled

    wkv_scan<<<(BB * DD) / 64, 64>>>(kb, vb, att_a, att_b, att_p,
                                     tm_decay, tm_first, wkv,
                                     aa_out, bb_out, pp_out);

    wconv_t<<<dim3(DD/32, DD/32), wt_thr>>>(Wo, wo, DD, DD);
    mul_h<<<ELT_BLOCKS, 256>>>(rb, wkv, av);            // av := fp16(r * wkv)
    GemmArgs go = mk(av, wo, DD, DD, x1, nullptr, 0, nullptr, x, 8);
    mma_gemm<<<dim3(8, 32, 1), 512, GEMM_SMEM>>>(go, go, go);

    // ---- channel mixing ----
    wconv_t<<<dim3(DD/32, DD/32), wt_thr>>>(Cr, cr, DD, DD);
    wconv_t<<<dim3(FF/32, DD/32), wt_thr>>>(Ck, ck, DD, FF);  // -> [FF,DD]
    wconv_t<<<dim3(DD/32, FF/32), wt_thr>>>(Cv, cv, FF, DD);  // -> [DD,FF]
    ln_kernel<<<MM, 256>>>(x1, ln2_g, ln2_b, xn2, xn2_last);
    mix_h<<<ELT_BLOCKS, 256>>>(xn2, ffn_x, cm_mix_k, nullptr, cm_mix_r,
                               ak, nullptr, ar);

    // Ck (z=0, 32 x-blocks) + Cr (z=1, 8 x-blocks) in one launch
    GemmArgs gck = mk(ak, ck, DD, FF, nullptr, kc, 2, nullptr, nullptr, 32);
    GemmArgs gcr = mk(ar, cr, DD, DD, rc, nullptr, 1, nullptr, nullptr, 8);
    mma_gemm<<<dim3(32, 32, 2), 512, GEMM_SMEM>>>(gck, gcr, gcr);

    GemmArgs gcv = mk(kc, cv, FF, DD, out, nullptr, 0, rc, x1, 8);
    mma_gemm<<<dim3(8, 32, 1), 512, GEMM_SMEM>>>(gcv, gcv, gcv);
}

// round 14
// speedup vs baseline: 1.1008x; 1.1008x over previous
#include <cuda_runtime.h>
#include <cuda_fp16.h>
#include <cuda_bf16.h>
#include <cstdint>

// ---------------- problem constants ----------------
#define BB 8
#define TT 1024
#define DD 1024
#define FF 4096
#define MM (BB * TT)          // 8192 rows
#define EPS_LN 1e-3f

// ---------------- PTX helpers ----------------
__device__ __forceinline__ uint32_t smem_u32(const void* p) {
    uint32_t a;
    asm("{ .reg .u64 t; cvta.to.shared.u64 t, %1; cvt.u32.u64 %0, t; }"
        : "=r"(a) : "l"(p));
    return a;
}

__device__ __forceinline__ void cpa16(uint32_t dst, const void* src) {
    asm volatile("cp.async.cg.shared.global [%0], [%1], 16;"
                 :: "r"(dst), "l"(src) : "memory");
}
#define CP_COMMIT() asm volatile("cp.async.commit_group;" ::: "memory")
#define CP_WAIT(n)  asm volatile("cp.async.wait_group %0;" :: "n"(n) : "memory")

__device__ __forceinline__ void ldsm4(uint32_t* r, uint32_t a) {
    asm volatile("ldmatrix.sync.aligned.m8n8.x4.shared.b16 {%0,%1,%2,%3}, [%4];"
                 : "=r"(r[0]), "=r"(r[1]), "=r"(r[2]), "=r"(r[3]) : "r"(a));
}

__device__ __forceinline__ void mma_fp16(float* c, const uint32_t* a, const uint32_t* b) {
    asm volatile(
        "mma.sync.aligned.m16n8k16.row.col.f32.f16.f16.f32 "
        "{%0,%1,%2,%3}, {%4,%5,%6,%7}, {%8,%9}, {%0,%1,%2,%3};"
        : "+f"(c[0]), "+f"(c[1]), "+f"(c[2]), "+f"(c[3])
        : "r"(a[0]), "r"(a[1]), "r"(a[2]), "r"(a[3]), "r"(b[0]), "r"(b[1]));
}

// ---------------- scratch (static device globals) ----------------
__device__ float g_kb [(size_t)MM * DD];
__device__ float g_vb [(size_t)MM * DD];
__device__ float g_rb [(size_t)MM * DD];
__device__ float g_x1 [(size_t)MM * DD];
__device__ float g_rc [(size_t)MM * DD];
// fp16 activations
__device__ __half g_ak[(size_t)MM * DD];
__device__ __half g_av[(size_t)MM * DD];
__device__ __half g_ar[(size_t)MM * DD];
__device__ __half g_kc[(size_t)MM * FF];
// fp16 transposed weights [N, K]
__device__ __half g_wk[(size_t)DD * DD];
__device__ __half g_wv[(size_t)DD * DD];
__device__ __half g_wr[(size_t)DD * DD];
__device__ __half g_wo[(size_t)DD * DD];
__device__ __half g_cr[(size_t)DD * DD];
__device__ __half g_ck[(size_t)FF * DD];   // Ck^T
__device__ __half g_cv[(size_t)DD * FF];   // Cv^T

// ---------------- fused LayerNorm + token-shift mix -> fp16 ----------------
// One block per row. Computes LN(x[row]) and LN(x[row-1]) (or uses init state
// for t==0), then the mix outputs. LN is deterministic, so recomputing the
// previous row's stats yields bit-identical values to a two-pass scheme.
__global__ __launch_bounds__(256)
void ln_mix(const float* __restrict__ x, const float* __restrict__ init,
            const float* __restrict__ gamma, const float* __restrict__ beta,
            const float* __restrict__ mk, const float* __restrict__ mv,
            const float* __restrict__ mr,
            __half* __restrict__ ok, __half* __restrict__ ov,
            __half* __restrict__ orr,
            float* __restrict__ last_out) {
    __shared__ float red[4][8];
    int row = blockIdx.x;
    int t = row & (TT - 1);
    int b = row >> 10;
    const float* xr = x + (size_t)row * DD;
    const float* xp = xr - DD;            // valid only when t > 0
    bool has_prev = (t > 0);

    float s = 0.f, s2 = 0.f, ps = 0.f, ps2 = 0.f;
    for (int i = threadIdx.x; i < DD; i += 256) {
        float v = xr[i];
        s += v; s2 += v * v;
        if (has_prev) {
            float u = xp[i];
            ps += u; ps2 += u * u;
        }
    }
    #pragma unroll
    for (int o = 16; o; o >>= 1) {
        s   += __shfl_down_sync(0xffffffffu, s,   o);
        s2  += __shfl_down_sync(0xffffffffu, s2,  o);
        ps  += __shfl_down_sync(0xffffffffu, ps,  o);
        ps2 += __shfl_down_sync(0xffffffffu, ps2, o);
    }
    int lane = threadIdx.x & 31, wid = threadIdx.x >> 5;
    if (lane == 0) {
        red[0][wid] = s; red[1][wid] = s2; red[2][wid] = ps; red[3][wid] = ps2;
    }
    __syncthreads();
    s = 0.f; s2 = 0.f; ps = 0.f; ps2 = 0.f;
    #pragma unroll
    for (int i = 0; i < 8; i++) {
        s += red[0][i]; s2 += red[1][i]; ps += red[2][i]; ps2 += red[3][i];
    }
    const float invD = 1.0f / DD;
    float mu   = s * invD;
    float var  = s2 * invD - mu * mu;
    float inv  = rsqrtf(var + EPS_LN);
    float pmu  = ps * invD;
    float pvar = ps2 * invD - pmu * pmu;
    float pinv = rsqrtf(pvar + EPS_LN);

    bool is_last = (t == (TT - 1));
    float* lr = last_out + (size_t)b * DD;
    const float* ir = init + (size_t)b * DD;

    for (int i = threadIdx.x; i < DD; i += 256) {
        float gi = gamma[i], bi = beta[i];
        float cur  = (xr[i] - mu) * inv * gi + bi;
        float prev = has_prev ? (xp[i] - pmu) * pinv * gi + bi : ir[i];
        float m;
        m = mk[i]; ok[(size_t)row * DD + i]  = __float2half(m * cur + (1.f - m) * prev);
        if (ov) { m = mv[i]; ov[(size_t)row * DD + i] = __float2half(m * cur + (1.f - m) * prev); }
        m = mr[i]; orr[(size_t)row * DD + i] = __float2half(m * cur + (1.f - m) * prev);
        if (is_last) lr[i] = cur;
    }
}

// ---------------- weight convert + transpose: W[K,N] fp32 -> WT [N,K] fp16 ----------------
__global__ __launch_bounds__(256)
void wconv_t(const float* __restrict__ W, __half* __restrict__ o,
             int Kdim, int Ndim) {
    __shared__ float t[32][33];
    int n0 = blockIdx.x * 32, k0 = blockIdx.y * 32;
    int tx = threadIdx.x, ty = threadIdx.y;
    #pragma unroll
    for (int i = ty; i < 32; i += 8)
        t[i][tx] = W[(size_t)(k0 + i) * Ndim + n0 + tx];
    __syncthreads();
    #pragma unroll
    for (int i = ty; i < 32; i += 8)
        o[(size_t)(n0 + i) * Kdim + k0 + tx] = __float2half(t[tx][i]);
}

// ---------------- WKV scan (fused r-multiply, fp16 output) ----------------
__global__ __launch_bounds__(64)
void wkv_scan(const float* __restrict__ kbuf, const float* __restrict__ vbuf,
              const float* __restrict__ rbuf,
              const float* __restrict__ a0, const float* __restrict__ b0,
              const float* __restrict__ p0,
              const float* __restrict__ decay, const float* __restrict__ first,
              __half* __restrict__ av_out,
              float* __restrict__ aa_out, float* __restrict__ bb_out,
              float* __restrict__ pp_out) {
    int idx = blockIdx.x * 64 + threadIdx.x;   // 0 .. B*D-1
    int d = idx & (DD - 1);
    int b = idx >> 10;
    float w = -__expf(decay[d]);
    float u = first[d];
    float aa = a0[idx], bb = b0[idx], pp = p0[idx];
    const float* kp = kbuf + (size_t)b * TT * DD + d;
    const float* vp = vbuf + (size_t)b * TT * DD + d;
    const float* rp = rbuf + (size_t)b * TT * DD + d;
    __half* op = av_out + (size_t)b * TT * DD + d;
    #pragma unroll 4
    for (int t = 0; t < TT; t++) {
        float kt = kp[(size_t)t * DD];
        float vt = vp[(size_t)t * DD];
        float ww = u + kt;
        float p  = fmaxf(pp, ww);
        float e1 = __expf(pp - p);
        float e2 = __expf(ww - p);
        float wkv = (e1 * aa + e2 * vt) / (e1 * bb + e2);
        op[(size_t)t * DD] = __float2half(rp[(size_t)t * DD] * wkv);
        float ww2 = pp + w;
        float p2  = fmaxf(ww2, kt);
        float e1b = __expf(ww2 - p2);
        float e2b = __expf(kt - p2);
        aa = e1b * aa + e2b * vt;
        bb = e1b * bb + e2b;
        pp = p2;
    }
    aa_out[idx] = aa; bb_out[idx] = bb; pp_out[idx] = pp;
}

// ---------------- fp16 mma.sync GEMM: C[M,N] = A[M,K] @ W^T (W stored [N,K]) ----------------
// CTA tile 256x128, BK=32, 512 threads / 16 warps (warp tile 64x32), 5-stage cp.async.
#define ROWP 80                         // smem row pitch bytes (32 fp16 + 8 pad)
#define OFF_B 20480                     // A = 256*80
#define STAGEB 30720                    // A + B
#define NSTAGE 5
#define GEMM_SMEM (NSTAGE * STAGEB)     // 153600

__device__ __forceinline__ void epi_pair(float v0, float v1, size_t base,
                                         int act,
                                         const float* __restrict__ mulp,
                                         const float* __restrict__ addp,
                                         float* __restrict__ Cf,
                                         __half* __restrict__ Ch) {
    if (act == 1) {
        v0 = 1.f / (1.f + __expf(-v0));
        v1 = 1.f / (1.f + __expf(-v1));
    } else if (act == 2) {
        v0 = fmaxf(v0, 0.f); v0 *= v0;
        v1 = fmaxf(v1, 0.f); v1 *= v1;
    }
    if (mulp) { float2 m = *(const float2*)(mulp + base); v0 *= m.x; v1 *= m.y; }
    if (addp) { float2 a = *(const float2*)(addp + base); v0 += a.x; v1 += a.y; }
    if (Cf) { float2 o; o.x = v0; o.y = v1; *(float2*)(Cf + base) = o; }
    if (Ch) {
        __half2 h = __floats2half2_rn(v0, v1);
        *(__half2*)(Ch + base) = h;
    }
}

__global__ __launch_bounds__(512, 1)
void mma_gemm(const __half* __restrict__ A, const __half* __restrict__ Bw,
              int Kn, int Nn,
              float* __restrict__ Cf, __half* __restrict__ Ch,
              int act, const float* __restrict__ mulp, const float* __restrict__ addp) {
    extern __shared__ char sm[];
    const uint32_t sbase = smem_u32(sm);
    const int tid = threadIdx.x;
    const int lane = tid & 31, wid = tid >> 5;
    const int m0 = blockIdx.y * 256, n0 = blockIdx.x * 128;
    const int KT = Kn >> 5;
    const int wm = (wid >> 2) * 64;   // warp m offset (0..192)
    const int wn = (wid & 3) * 32;    // warp n offset (0..96)

    float acc[4][4][4];
    #pragma unroll
    for (int t = 0; t < 4; t++)
        #pragma unroll
        for (int j = 0; j < 4; j++)
            #pragma unroll
            for (int q = 0; q < 4; q++) acc[t][j][q] = 0.f;

    auto issue = [&](int kt) {
        const int slot = kt % NSTAGE;
        const uint32_t st = sbase + slot * STAGEB;
        const size_t k0 = (size_t)kt << 5;
        #pragma unroll
        for (int h = 0; h < 2; h++) {
            int idx = tid + h * 512;
            int row = idx >> 2, ch = idx & 3;
            cpa16(st + (uint32_t)row * ROWP + ch * 16,
                  A + (size_t)(m0 + row) * Kn + k0 + ch * 8);
        }
        {
            int row = tid >> 2, ch = tid & 3;
            cpa16(st + OFF_B + (uint32_t)row * ROWP + ch * 16,
                  Bw + (size_t)(n0 + row) * Kn + k0 + ch * 8);
        }
        CP_COMMIT();
    };

    issue(0);
    issue(1);
    issue(2);
    issue(3);

    for (int kt = 0; kt < KT; kt++) {
        CP_WAIT(3);
        __syncthreads();
        const uint32_t st = sbase + (kt % NSTAGE) * STAGEB;
        #pragma unroll
        for (int ks = 0; ks < 2; ks++) {
            const int k0 = ks * 16;
            uint32_t ah[4][4], bh[4][2];
            #pragma unroll
            for (int t = 0; t < 4; t++) {
                uint32_t ad = st + (uint32_t)(wm + t * 16 + (lane & 15)) * ROWP
                            + (k0 + (lane >> 4) * 8) * 2;
                ldsm4(ah[t], ad);
            }
            {
                int g = lane >> 3, r = lane & 7;
                int n = wn + (g >> 1) * 8 + r;
                int k = k0 + (g & 1) * 8;
                uint32_t bd = st + OFF_B + (uint32_t)n * ROWP + k * 2;
                ldsm4(&bh[0][0], bd);
                ldsm4(&bh[2][0], bd + 16 * ROWP);
            }
            #pragma unroll
            for (int t = 0; t < 4; t++)
                #pragma unroll
                for (int j = 0; j < 4; j++)
                    mma_fp16(acc[t][j], ah[t], bh[j]);
        }
        if (kt + 4 < KT) issue(kt + 4);
    }
    CP_WAIT(0);

    // ---- epilogue ----
    #pragma unroll
    for (int t = 0; t < 4; t++) {
        int row = m0 + wm + t * 16 + (lane >> 2);
        #pragma unroll
        for (int j = 0; j < 4; j++) {
            int col = n0 + wn + j * 8 + ((lane & 3) << 1);
            size_t b0 = (size_t)row * Nn + col;
            size_t b1 = (size_t)(row + 8) * Nn + col;
            epi_pair(acc[t][j][0], acc[t][j][1], b0, act, mulp, addp, Cf, Ch);
            epi_pair(acc[t][j][2], acc[t][j][3], b1, act, mulp, addp, Cf, Ch);
        }
    }
}

// ---------------- host driver ----------------
extern "C" void kernel_launch(void* const* d_in, const int* in_sizes, int n_in,
                              void* d_out, int out_size) {
    const float* x        = (const float*)d_in[0];
    const float* att_x    = (const float*)d_in[1];
    const float* att_a    = (const float*)d_in[2];
    const float* att_b    = (const float*)d_in[3];
    const float* att_p    = (const float*)d_in[4];
    const float* ffn_x    = (const float*)d_in[5];
    const float* ln1_g    = (const float*)d_in[6];
    const float* ln1_b    = (const float*)d_in[7];
    const float* ln2_g    = (const float*)d_in[8];
    const float* ln2_b    = (const float*)d_in[9];
    const float* tm_mix_k = (const float*)d_in[10];
    const float* tm_mix_v = (const float*)d_in[11];
    const float* tm_mix_r = (const float*)d_in[12];
    const float* tm_decay = (const float*)d_in[13];
    const float* tm_first = (const float*)d_in[14];
    const float* Wk       = (const float*)d_in[15];
    const float* Wv       = (const float*)d_in[16];
    const float* Wr       = (const float*)d_in[17];
    const float* Wo       = (const float*)d_in[18];
    const float* cm_mix_k = (const float*)d_in[19];
    const float* cm_mix_r = (const float*)d_in[20];
    const float* Ck       = (const float*)d_in[21];
    const float* Cr       = (const float*)d_in[22];
    const float* Cv       = (const float*)d_in[23];

    float* out      = (float*)d_out;
    float* xn_last  = out + (size_t)MM * DD;
    float* aa_out   = xn_last  + (size_t)BB * DD;
    float* bb_out   = aa_out   + (size_t)BB * DD;
    float* pp_out   = bb_out   + (size_t)BB * DD;
    float* xn2_last = pp_out   + (size_t)BB * DD;

    float *kb, *vb, *rb, *x1, *rc;
    __half *ak, *av, *ar, *kc;
    __half *wk, *wv, *wr, *wo, *cr, *ck, *cv;
    cudaGetSymbolAddress((void**)&kb,  g_kb);
    cudaGetSymbolAddress((void**)&vb,  g_vb);
    cudaGetSymbolAddress((void**)&rb,  g_rb);
    cudaGetSymbolAddress((void**)&x1,  g_x1);
    cudaGetSymbolAddress((void**)&rc,  g_rc);
    cudaGetSymbolAddress((void**)&ak,  g_ak);
    cudaGetSymbolAddress((void**)&av,  g_av);
    cudaGetSymbolAddress((void**)&ar,  g_ar);
    cudaGetSymbolAddress((void**)&kc,  g_kc);
    cudaGetSymbolAddress((void**)&wk,  g_wk);
    cudaGetSymbolAddress((void**)&wv,  g_wv);
    cudaGetSymbolAddress((void**)&wr,  g_wr);
    cudaGetSymbolAddress((void**)&wo,  g_wo);
    cudaGetSymbolAddress((void**)&cr,  g_cr);
    cudaGetSymbolAddress((void**)&ck,  g_ck);
    cudaGetSymbolAddress((void**)&cv,  g_cv);

    cudaFuncSetAttribute(mma_gemm, cudaFuncAttributeMaxDynamicSharedMemorySize, GEMM_SMEM);

    dim3 wt_thr(32, 8);
    dim3 g1k(DD / 128, MM / 256);   // (8, 32)
    dim3 g4k(FF / 128, MM / 256);   // (32, 32)

    // ---- time mixing ----
    wconv_t<<<dim3(DD/32, DD/32), wt_thr>>>(Wk, wk, DD, DD);                  // 0
    wconv_t<<<dim3(DD/32, DD/32), wt_thr>>>(Wv, wv, DD, DD);                  // 1
    wconv_t<<<dim3(DD/32, DD/32), wt_thr>>>(Wr, wr, DD, DD);                  // 2
    ln_mix<<<MM, 256>>>(x, att_x, ln1_g, ln1_b,
                        tm_mix_k, tm_mix_v, tm_mix_r,
                        ak, av, ar, xn_last);                                 // 3
    mma_gemm<<<g1k, 512, GEMM_SMEM>>>(ak, wk, DD, DD,
                                      kb, nullptr, 0, nullptr, nullptr);      // 4
    mma_gemm<<<g1k, 512, GEMM_SMEM>>>(av, wv, DD, DD,
                                      vb, nullptr, 0, nullptr, nullptr);      // 5 <- profiled
    mma_gemm<<<g1k, 512, GEMM_SMEM>>>(ar, wr, DD, DD,
                                      rb, nullptr, 1, nullptr, nullptr);

    wkv_scan<<<(BB * DD) / 64, 64>>>(kb, vb, rb, att_a, att_b, att_p,
                                     tm_decay, tm_first, av,
                                     aa_out, bb_out, pp_out);

    wconv_t<<<dim3(DD/32, DD/32), wt_thr>>>(Wo, wo, DD, DD);
    mma_gemm<<<g1k, 512, GEMM_SMEM>>>(av, wo, DD, DD,
                                      x1, nullptr, 0, nullptr, x);

    // ---- channel mixing ----
    wconv_t<<<dim3(DD/32, DD/32), wt_thr>>>(Cr, cr, DD, DD);
    wconv_t<<<dim3(FF/32, DD/32), wt_thr>>>(Ck, ck, DD, FF);  // -> [FF,DD]
    wconv_t<<<dim3(DD/32, FF/32), wt_thr>>>(Cv, cv, FF, DD);  // -> [DD,FF]
    ln_mix<<<MM, 256>>>(x1, ffn_x, ln2_g, ln2_b,
                        cm_mix_k, nullptr, cm_mix_r,
                        ak, nullptr, ar, xn2_last);
    mma_gemm<<<g4k, 512, GEMM_SMEM>>>(ak, ck, DD, FF,
                                      nullptr, kc, 2, nullptr, nullptr);  // relu^2 -> fp16
    mma_gemm<<<g1k, 512, GEMM_SMEM>>>(ar, cr, DD, DD,
                                      rc, nullptr, 1, nullptr, nullptr);
    mma_gemm<<<g1k, 512, GEMM_SMEM>>>(kc, cv, FF, DD,
                                      out, nullptr, 0, rc, x1);
}

// round 15
// speedup vs baseline: 1.1337x; 1.0298x over previous
#include <cuda_runtime.h>
#include <cuda_fp16.h>
#include <cuda_bf16.h>
#include <cstdint>

// ---------------- problem constants ----------------
#define BB 8
#define TT 1024
#define DD 1024
#define FF 4096
#define MM (BB * TT)          // 8192 rows
#define EPS_LN 1e-3f

// ---------------- PTX helpers ----------------
__device__ __forceinline__ uint32_t smem_u32(const void* p) {
    uint32_t a;
    asm("{ .reg .u64 t; cvta.to.shared.u64 t, %1; cvt.u32.u64 %0, t; }"
        : "=r"(a) : "l"(p));
    return a;
}

__device__ __forceinline__ void cpa16(uint32_t dst, const void* src) {
    asm volatile("cp.async.cg.shared.global [%0], [%1], 16;"
                 :: "r"(dst), "l"(src) : "memory");
}
#define CP_COMMIT() asm volatile("cp.async.commit_group;" ::: "memory")
#define CP_WAIT(n)  asm volatile("cp.async.wait_group %0;" :: "n"(n) : "memory")

__device__ __forceinline__ void ldsm4(uint32_t* r, uint32_t a) {
    asm volatile("ldmatrix.sync.aligned.m8n8.x4.shared.b16 {%0,%1,%2,%3}, [%4];"
                 : "=r"(r[0]), "=r"(r[1]), "=r"(r[2]), "=r"(r[3]) : "r"(a));
}

// NON-volatile: pure register function; data dependencies provide ordering.
// Lets ptxas software-pipeline MMAs across ldsm latency.
__device__ __forceinline__ void mma_fp16(float* c, const uint32_t* a, const uint32_t* b) {
    asm("mma.sync.aligned.m16n8k16.row.col.f32.f16.f16.f32 "
        "{%0,%1,%2,%3}, {%4,%5,%6,%7}, {%8,%9}, {%0,%1,%2,%3};"
        : "+f"(c[0]), "+f"(c[1]), "+f"(c[2]), "+f"(c[3])
        : "r"(a[0]), "r"(a[1]), "r"(a[2]), "r"(a[3]), "r"(b[0]), "r"(b[1]));
}

// ---------------- scratch (static device globals) ----------------
__device__ float g_xn [(size_t)MM * DD];
__device__ float g_kb [(size_t)MM * DD];
__device__ float g_vb [(size_t)MM * DD];
__device__ float g_rb [(size_t)MM * DD];
__device__ float g_x1 [(size_t)MM * DD];
__device__ float g_xn2[(size_t)MM * DD];
__device__ float g_rc [(size_t)MM * DD];
// fp16 activations
__device__ __half g_ak[(size_t)MM * DD];
__device__ __half g_av[(size_t)MM * DD];
__device__ __half g_ar[(size_t)MM * DD];
__device__ __half g_kc[(size_t)MM * FF];
// fp16 transposed weights [N, K]
__device__ __half g_wk[(size_t)DD * DD];
__device__ __half g_wv[(size_t)DD * DD];
__device__ __half g_wr[(size_t)DD * DD];
__device__ __half g_wo[(size_t)DD * DD];
__device__ __half g_cr[(size_t)DD * DD];
__device__ __half g_ck[(size_t)FF * DD];   // Ck^T
__device__ __half g_cv[(size_t)DD * FF];   // Cv^T

// ---------------- LayerNorm ----------------
__global__ __launch_bounds__(256)
void ln_kernel(const float* __restrict__ x, const float* __restrict__ gamma,
               const float* __restrict__ beta, float* __restrict__ y,
               float* __restrict__ last_out) {
    __shared__ float red0[8], red1[8];
    int row = blockIdx.x;
    const float* xr = x + (size_t)row * DD;
    float s = 0.f, s2 = 0.f;
    #pragma unroll
    for (int i = threadIdx.x; i < DD; i += 256) {
        float v = xr[i];
        s += v; s2 += v * v;
    }
    #pragma unroll
    for (int o = 16; o; o >>= 1) {
        s  += __shfl_down_sync(0xffffffffu, s,  o);
        s2 += __shfl_down_sync(0xffffffffu, s2, o);
    }
    int lane = threadIdx.x & 31, wid = threadIdx.x >> 5;
    if (lane == 0) { red0[wid] = s; red1[wid] = s2; }
    __syncthreads();
    s = 0.f; s2 = 0.f;
    #pragma unroll
    for (int i = 0; i < 8; i++) { s += red0[i]; s2 += red1[i]; }
    const float invD = 1.0f / DD;
    float mu  = s * invD;
    float var = s2 * invD - mu * mu;
    float inv = rsqrtf(var + EPS_LN);
    float* yr = y + (size_t)row * DD;
    bool is_last = ((row & (TT - 1)) == (TT - 1));
    float* lr = last_out + (size_t)(row >> 10) * DD;
    #pragma unroll
    for (int i = threadIdx.x; i < DD; i += 256) {
        float v = (xr[i] - mu) * inv * gamma[i] + beta[i];
        yr[i] = v;
        if (is_last) lr[i] = v;
    }
}

// ---------------- token-shift mix -> fp16 ----------------
__global__ __launch_bounds__(256)
void mix_h(const float* __restrict__ xn, const float* __restrict__ init,
           const float* __restrict__ mk, const float* __restrict__ mv,
           const float* __restrict__ mr,
           __half* __restrict__ ok, __half* __restrict__ ov,
           __half* __restrict__ orr) {
    size_t idx = (size_t)blockIdx.x * 256 + threadIdx.x;
    int d = (int)(idx & (DD - 1));
    size_t row = idx >> 10;
    int t = (int)(row & (TT - 1));
    int b = (int)(row >> 10);
    float cur  = xn[idx];
    float prev = t ? xn[idx - DD] : init[(size_t)b * DD + d];
    float m;
    m = mk[d]; ok[idx]  = __float2half(m * cur + (1.f - m) * prev);
    if (ov) { m = mv[d]; ov[idx] = __float2half(m * cur + (1.f - m) * prev); }
    m = mr[d]; orr[idx] = __float2half(m * cur + (1.f - m) * prev);
}

// ---------------- weight convert + transpose: W[K,N] fp32 -> WT [N,K] fp16 ----------------
__global__ __launch_bounds__(256)
void wconv_t(const float* __restrict__ W, __half* __restrict__ o,
             int Kdim, int Ndim) {
    __shared__ float t[32][33];
    int n0 = blockIdx.x * 32, k0 = blockIdx.y * 32;
    int tx = threadIdx.x, ty = threadIdx.y;
    #pragma unroll
    for (int i = ty; i < 32; i += 8)
        t[i][tx] = W[(size_t)(k0 + i) * Ndim + n0 + tx];
    __syncthreads();
    #pragma unroll
    for (int i = ty; i < 32; i += 8)
        o[(size_t)(n0 + i) * Kdim + k0 + tx] = __float2half(t[tx][i]);
}

// ---------------- WKV scan (fused r-multiply, fp16 output) ----------------
__global__ __launch_bounds__(64)
void wkv_scan(const float* __restrict__ kbuf, const float* __restrict__ vbuf,
              const float* __restrict__ rbuf,
              const float* __restrict__ a0, const float* __restrict__ b0,
              const float* __restrict__ p0,
              const float* __restrict__ decay, const float* __restrict__ first,
              __half* __restrict__ av_out,
              float* __restrict__ aa_out, float* __restrict__ bb_out,
              float* __restrict__ pp_out) {
    int idx = blockIdx.x * 64 + threadIdx.x;   // 0 .. B*D-1
    int d = idx & (DD - 1);
    int b = idx >> 10;
    float w = -__expf(decay[d]);
    float u = first[d];
    float aa = a0[idx], bb = b0[idx], pp = p0[idx];
    const float* kp = kbuf + (size_t)b * TT * DD + d;
    const float* vp = vbuf + (size_t)b * TT * DD + d;
    const float* rp = rbuf + (size_t)b * TT * DD + d;
    __half* op = av_out + (size_t)b * TT * DD + d;
    #pragma unroll 4
    for (int t = 0; t < TT; t++) {
        float kt = kp[(size_t)t * DD];
        float vt = vp[(size_t)t * DD];
        float ww = u + kt;
        float p  = fmaxf(pp, ww);
        float e1 = __expf(pp - p);
        float e2 = __expf(ww - p);
        float wkv = (e1 * aa + e2 * vt) / (e1 * bb + e2);
        op[(size_t)t * DD] = __float2half(rp[(size_t)t * DD] * wkv);
        float ww2 = pp + w;
        float p2  = fmaxf(ww2, kt);
        float e1b = __expf(ww2 - p2);
        float e2b = __expf(kt - p2);
        aa = e1b * aa + e2b * vt;
        bb = e1b * bb + e2b;
        pp = p2;
    }
    aa_out[idx] = aa; bb_out[idx] = bb; pp_out[idx] = pp;
}

// ---------------- fp16 mma.sync GEMM: C[M,N] = A[M,K] @ W^T (W stored [N,K]) ----------------
// CTA tile 256x128, BK=32, 512 threads / 16 warps (warp tile 64x32), 5-stage cp.async.
#define ROWP 80                         // smem row pitch bytes (32 fp16 + 8 pad)
#define OFF_B 20480                     // A = 256*80
#define STAGEB 30720                    // A + B
#define NSTAGE 5
#define GEMM_SMEM (NSTAGE * STAGEB)     // 153600

__device__ __forceinline__ void epi_pair(float v0, float v1, size_t base,
                                         int act,
                                         const float* __restrict__ mulp,
                                         const float* __restrict__ addp,
                                         float* __restrict__ Cf,
                                         __half* __restrict__ Ch) {
    if (act == 1) {
        v0 = 1.f / (1.f + __expf(-v0));
        v1 = 1.f / (1.f + __expf(-v1));
    } else if (act == 2) {
        v0 = fmaxf(v0, 0.f); v0 *= v0;
        v1 = fmaxf(v1, 0.f); v1 *= v1;
    }
    if (mulp) { float2 m = *(const float2*)(mulp + base); v0 *= m.x; v1 *= m.y; }
    if (addp) { float2 a = *(const float2*)(addp + base); v0 += a.x; v1 += a.y; }
    if (Cf) { float2 o; o.x = v0; o.y = v1; *(float2*)(Cf + base) = o; }
    if (Ch) {
        __half2 h = __floats2half2_rn(v0, v1);
        *(__half2*)(Ch + base) = h;
    }
}

__global__ __launch_bounds__(512, 1)
void mma_gemm(const __half* __restrict__ A, const __half* __restrict__ Bw,
              int Kn, int Nn,
              float* __restrict__ Cf, __half* __restrict__ Ch,
              int act, const float* __restrict__ mulp, const float* __restrict__ addp) {
    extern __shared__ char sm[];
    const uint32_t sbase = smem_u32(sm);
    const int tid = threadIdx.x;
    const int lane = tid & 31, wid = tid >> 5;
    const int m0 = blockIdx.y * 256, n0 = blockIdx.x * 128;
    const int KT = Kn >> 5;
    const int wm = (wid >> 2) * 64;   // warp m offset (0..192)
    const int wn = (wid & 3) * 32;    // warp n offset (0..96)

    float acc[4][4][4];
    #pragma unroll
    for (int t = 0; t < 4; t++)
        #pragma unroll
        for (int j = 0; j < 4; j++)
            #pragma unroll
            for (int q = 0; q < 4; q++) acc[t][j][q] = 0.f;

    auto issue = [&](int kt) {
        const int slot = kt % NSTAGE;
        const uint32_t st = sbase + slot * STAGEB;
        const size_t k0 = (size_t)kt << 5;
        #pragma unroll
        for (int h = 0; h < 2; h++) {
            int idx = tid + h * 512;
            int row = idx >> 2, ch = idx & 3;
            cpa16(st + (uint32_t)row * ROWP + ch * 16,
                  A + (size_t)(m0 + row) * Kn + k0 + ch * 8);
        }
        {
            int row = tid >> 2, ch = tid & 3;
            cpa16(st + OFF_B + (uint32_t)row * ROWP + ch * 16,
                  Bw + (size_t)(n0 + row) * Kn + k0 + ch * 8);
        }
        CP_COMMIT();
    };

    issue(0);
    issue(1);
    issue(2);
    issue(3);

    for (int kt = 0; kt < KT; kt++) {
        CP_WAIT(3);
        __syncthreads();
        const uint32_t st = sbase + (kt % NSTAGE) * STAGEB;
        #pragma unroll
        for (int ks = 0; ks < 2; ks++) {
            const int k0 = ks * 16;
            uint32_t ah[4][4], bh[4][2];
            #pragma unroll
            for (int t = 0; t < 4; t++) {
                uint32_t ad = st + (uint32_t)(wm + t * 16 + (lane & 15)) * ROWP
                            + (k0 + (lane >> 4) * 8) * 2;
                ldsm4(ah[t], ad);
            }
            {
                int g = lane >> 3, r = lane & 7;
                int n = wn + (g >> 1) * 8 + r;
                int k = k0 + (g & 1) * 8;
                uint32_t bd = st + OFF_B + (uint32_t)n * ROWP + k * 2;
                ldsm4(&bh[0][0], bd);
                ldsm4(&bh[2][0], bd + 16 * ROWP);
            }
            #pragma unroll
            for (int t = 0; t < 4; t++)
                #pragma unroll
                for (int j = 0; j < 4; j++)
                    mma_fp16(acc[t][j], ah[t], bh[j]);
        }
        if (kt + 4 < KT) issue(kt + 4);
    }
    CP_WAIT(0);

    // ---- epilogue ----
    #pragma unroll
    for (int t = 0; t < 4; t++) {
        int row = m0 + wm + t * 16 + (lane >> 2);
        #pragma unroll
        for (int j = 0; j < 4; j++) {
            int col = n0 + wn + j * 8 + ((lane & 3) << 1);
            size_t b0 = (size_t)row * Nn + col;
            size_t b1 = (size_t)(row + 8) * Nn + col;
            epi_pair(acc[t][j][0], acc[t][j][1], b0, act, mulp, addp, Cf, Ch);
            epi_pair(acc[t][j][2], acc[t][j][3], b1, act, mulp, addp, Cf, Ch);
        }
    }
}

// ---------------- host driver ----------------
extern "C" void kernel_launch(void* const* d_in, const int* in_sizes, int n_in,
                              void* d_out, int out_size) {
    const float* x        = (const float*)d_in[0];
    const float* att_x    = (const float*)d_in[1];
    const float* att_a    = (const float*)d_in[2];
    const float* att_b    = (const float*)d_in[3];
    const float* att_p    = (const float*)d_in[4];
    const float* ffn_x    = (const float*)d_in[5];
    const float* ln1_g    = (const float*)d_in[6];
    const float* ln1_b    = (const float*)d_in[7];
    const float* ln2_g    = (const float*)d_in[8];
    const float* ln2_b    = (const float*)d_in[9];
    const float* tm_mix_k = (const float*)d_in[10];
    const float* tm_mix_v = (const float*)d_in[11];
    const float* tm_mix_r = (const float*)d_in[12];
    const float* tm_decay = (const float*)d_in[13];
    const float* tm_first = (const float*)d_in[14];
    const float* Wk       = (const float*)d_in[15];
    const float* Wv       = (const float*)d_in[16];
    const float* Wr       = (const float*)d_in[17];
    const float* Wo       = (const float*)d_in[18];
    const float* cm_mix_k = (const float*)d_in[19];
    const float* cm_mix_r = (const float*)d_in[20];
    const float* Ck       = (const float*)d_in[21];
    const float* Cr       = (const float*)d_in[22];
    const float* Cv       = (const float*)d_in[23];

    float* out      = (float*)d_out;
    float* xn_last  = out + (size_t)MM * DD;
    float* aa_out   = xn_last  + (size_t)BB * DD;
    float* bb_out   = aa_out   + (size_t)BB * DD;
    float* pp_out   = bb_out   + (size_t)BB * DD;
    float* xn2_last = pp_out   + (size_t)BB * DD;

    float *xn, *kb, *vb, *rb, *x1, *xn2, *rc;
    __half *ak, *av, *ar, *kc;
    __half *wk, *wv, *wr, *wo, *cr, *ck, *cv;
    cudaGetSymbolAddress((void**)&xn,  g_xn);
    cudaGetSymbolAddress((void**)&kb,  g_kb);
    cudaGetSymbolAddress((void**)&vb,  g_vb);
    cudaGetSymbolAddress((void**)&rb,  g_rb);
    cudaGetSymbolAddress((void**)&x1,  g_x1);
    cudaGetSymbolAddress((void**)&xn2, g_xn2);
    cudaGetSymbolAddress((void**)&rc,  g_rc);
    cudaGetSymbolAddress((void**)&ak,  g_ak);
    cudaGetSymbolAddress((void**)&av,  g_av);
    cudaGetSymbolAddress((void**)&ar,  g_ar);
    cudaGetSymbolAddress((void**)&kc,  g_kc);
    cudaGetSymbolAddress((void**)&wk,  g_wk);
    cudaGetSymbolAddress((void**)&wv,  g_wv);
    cudaGetSymbolAddress((void**)&wr,  g_wr);
    cudaGetSymbolAddress((void**)&wo,  g_wo);
    cudaGetSymbolAddress((void**)&cr,  g_cr);
    cudaGetSymbolAddress((void**)&ck,  g_ck);
    cudaGetSymbolAddress((void**)&cv,  g_cv);

    cudaFuncSetAttribute(mma_gemm, cudaFuncAttributeMaxDynamicSharedMemorySize, GEMM_SMEM);

    const int ELT_BLOCKS = (int)(((size_t)MM * DD) / 256);  // 32768
    dim3 wt_thr(32, 8);
    dim3 g1k(DD / 128, MM / 256);   // (8, 32)
    dim3 g4k(FF / 128, MM / 256);   // (32, 32)

    // ---- time mixing ----
    wconv_t<<<dim3(DD/32, DD/32), wt_thr>>>(Wk, wk, DD, DD);
    wconv_t<<<dim3(DD/32, DD/32), wt_thr>>>(Wv, wv, DD, DD);
    wconv_t<<<dim3(DD/32, DD/32), wt_thr>>>(Wr, wr, DD, DD);
    ln_kernel<<<MM, 256>>>(x, ln1_g, ln1_b, xn, xn_last);
    mix_h<<<ELT_BLOCKS, 256>>>(xn, att_x, tm_mix_k, tm_mix_v, tm_mix_r,
                               ak, av, ar);
    mma_gemm<<<g1k, 512, GEMM_SMEM>>>(ak, wk, DD, DD,
                                      kb, nullptr, 0, nullptr, nullptr);
    mma_gemm<<<g1k, 512, GEMM_SMEM>>>(av, wv, DD, DD,
                                      vb, nullptr, 0, nullptr, nullptr);
    mma_gemm<<<g1k, 512, GEMM_SMEM>>>(ar, wr, DD, DD,
                                      rb, nullptr, 1, nullptr, nullptr);

    wkv_scan<<<(BB * DD) / 64, 64>>>(kb, vb, rb, att_a, att_b, att_p,
                                     tm_decay, tm_first, av,
                                     aa_out, bb_out, pp_out);

    wconv_t<<<dim3(DD/32, DD/32), wt_thr>>>(Wo, wo, DD, DD);
    mma_gemm<<<g1k, 512, GEMM_SMEM>>>(av, wo, DD, DD,
                                      x1, nullptr, 0, nullptr, x);

    // ---- channel mixing ----
    wconv_t<<<dim3(DD/32, DD/32), wt_thr>>>(Cr, cr, DD, DD);
    wconv_t<<<dim3(FF/32, DD/32), wt_thr>>>(Ck, ck, DD, FF);  // -> [FF,DD]
    wconv_t<<<dim3(DD/32, FF/32), wt_thr>>>(Cv, cv, FF, DD);  // -> [DD,FF]
    ln_kernel<<<MM, 256>>>(x1, ln2_g, ln2_b, xn2, xn2_last);
    mix_h<<<ELT_BLOCKS, 256>>>(xn2, ffn_x, cm_mix_k, nullptr, cm_mix_r,
                               ak, nullptr, ar);
    mma_gemm<<<g4k, 512, GEMM_SMEM>>>(ak, ck, DD, FF,
                                      nullptr, kc, 2, nullptr, nullptr);  // relu^2 -> fp16
    mma_gemm<<<g1k, 512, GEMM_SMEM>>>(ar, cr, DD, DD,
                                      rc, nullptr, 1, nullptr, nullptr);
    mma_gemm<<<g1k, 512, GEMM_SMEM>>>(kc, cv, FF, DD,
                                      out, nullptr, 0, rc, x1);
}